// round 7
// baseline (speedup 1.0000x reference)
#include <cuda_runtime.h>
#include <cuda_fp16.h>
#include <cstdint>

// ============================================================================
// y = x @ W^T + b (4096^3 fp32), mma.sync.m16n8k16.f32.f16.f16.f32.
//
// Round-7 == Round-6 with the prep_b grid fixed (16384 blocks: the 64-row
// B-block layout has 2^22 fragments; 8192 blocks only wrote half of g_wb,
// leaving the other half zero -> rel_err 1/sqrt(2)).
//
//  * CTA tile 128x64, 2 warps (64x64 warp tiles), 64 threads, 2 CTA/SM.
//    2048 CTAs -> 6.92 waves over 296 slots (quantization x1.012).
//  * Loads via single-thread cp.async.bulk (1D, contiguous fragment blocks)
//    into an 8-stage mbarrier full/empty pipeline. NO __syncthreads and NO
//    per-thread cp.async in the mainloop.
//  * Pre-pass converts fp32->fp16 (RN) into exact mma fragment order:
//      A'[m128][kb128][mt16:8][ks:2][lane:32][4xb32]   (8KB per (m128,kb))
//      B'[n64 ][kb128][nt8:8 ][ks:2][lane:32][2xb32]   (4KB per (n64,kb))
// ============================================================================

#define KDIM 4096
#define BK 32
#define STAGES 8
#define K_ITERS (KDIM / BK)               // 128
#define A_STG 8192                        // 128 x 32 x 2B
#define B_STG 4096                        // 64 x 32 x 2B
#define STG (A_STG + B_STG)               // 12288
#define SMEM_DATA 1024
#define SMEM_TOTAL (SMEM_DATA + STAGES * STG)   // 99328

__device__ __half g_xa[(size_t)KDIM * KDIM];   // A' fragment-ordered fp16
__device__ __half g_wb[(size_t)KDIM * KDIM];   // B' fragment-ordered fp16

// ---------------------------------------------------------------------------
__device__ __forceinline__ uint32_t smem_u32(const void* p) {
    uint32_t a;
    asm("{ .reg .u64 t; cvta.to.shared.u64 t, %1; cvt.u32.u64 %0, t; }"
        : "=r"(a) : "l"(p));
    return a;
}
__device__ __forceinline__ void mbar_init(uint32_t m, uint32_t cnt) {
    asm volatile("mbarrier.init.shared.b64 [%0], %1;" :: "r"(m), "r"(cnt) : "memory");
}
__device__ __forceinline__ void mbar_expect_tx(uint32_t m, uint32_t bytes) {
    asm volatile("mbarrier.arrive.expect_tx.shared.b64 _, [%0], %1;"
                 :: "r"(m), "r"(bytes) : "memory");
}
__device__ __forceinline__ void mbar_arrive(uint32_t m) {
    asm volatile("mbarrier.arrive.release.cta.shared.b64 _, [%0];" :: "r"(m) : "memory");
}
__device__ __forceinline__ void mbar_wait(uint32_t m, uint32_t parity) {
    asm volatile(
        "{\n\t.reg .pred P1;\n\t"
        "W_%=:\n\t"
        "mbarrier.try_wait.parity.acquire.cta.shared::cta.b64 P1, [%0], %1, 0x989680;\n\t"
        "@P1 bra.uni D_%=;\n\t"
        "bra.uni W_%=;\n\t"
        "D_%=:\n\t}"
        :: "r"(m), "r"(parity) : "memory");
}
__device__ __forceinline__ void bulk_ld(uint32_t dst, const void* src,
                                        uint32_t bytes, uint32_t mbar) {
    asm volatile(
        "cp.async.bulk.shared::cluster.global.mbarrier::complete_tx::bytes "
        "[%0], [%1], %2, [%3];"
        :: "r"(dst), "l"(src), "r"(bytes), "r"(mbar) : "memory");
}
__device__ __forceinline__ void lds128(uint32_t* r, uint32_t a) {
    asm volatile("ld.shared.v4.b32 {%0,%1,%2,%3}, [%4];"
                 : "=r"(r[0]), "=r"(r[1]), "=r"(r[2]), "=r"(r[3]) : "r"(a));
}
__device__ __forceinline__ void lds64(uint32_t* r, uint32_t a) {
    asm volatile("ld.shared.v2.b32 {%0,%1}, [%2];"
                 : "=r"(r[0]), "=r"(r[1]) : "r"(a));
}
__device__ __forceinline__ void mma_f16(float* c, const uint32_t* a, const uint32_t* b) {
    asm volatile(
        "mma.sync.aligned.m16n8k16.row.col.f32.f16.f16.f32 "
        "{%0,%1,%2,%3}, {%4,%5,%6,%7}, {%8,%9}, {%0,%1,%2,%3};"
        : "+f"(c[0]), "+f"(c[1]), "+f"(c[2]), "+f"(c[3])
        : "r"(a[0]), "r"(a[1]), "r"(a[2]), "r"(a[3]), "r"(b[0]), "r"(b[1]));
}
__device__ __forceinline__ uint32_t pack_h2(float lo, float hi) {
    __half2 h = __floats2half2_rn(lo, hi);
    return *reinterpret_cast<uint32_t*>(&h);
}

// ---------------------------------------------------------------------------
// Pre-pass A: one 16B fragment (8 halves) per thread.
// idx: [m128:5][kb:7][mt16:3][ks:1][lane:5]  -> 2,097,152 threads
// ---------------------------------------------------------------------------
__global__ void __launch_bounds__(256) prep_a(const float* __restrict__ src,
                                              uint4* __restrict__ dst) {
    const int idx  = blockIdx.x * 256 + threadIdx.x;
    const int lane = idx & 31;
    const int ks   = (idx >> 5) & 1;
    const int mt16 = (idx >> 6) & 7;
    const int kb   = (idx >> 9) & 127;
    const int m128 = idx >> 16;
    const int row = m128 * 128 + mt16 * 16 + (lane >> 2);
    const int col = kb * 32 + ks * 16 + (lane & 3) * 2;
    const float* p = src + (size_t)row * KDIM + col;
    const float2 v00 = *reinterpret_cast<const float2*>(p);
    const float2 v10 = *reinterpret_cast<const float2*>(p + (size_t)8 * KDIM);
    const float2 v01 = *reinterpret_cast<const float2*>(p + 8);
    const float2 v11 = *reinterpret_cast<const float2*>(p + (size_t)8 * KDIM + 8);
    uint4 o;
    o.x = pack_h2(v00.x, v00.y);
    o.y = pack_h2(v10.x, v10.y);
    o.z = pack_h2(v01.x, v01.y);
    o.w = pack_h2(v11.x, v11.y);
    dst[idx] = o;
}

// Pre-pass B: one 8B fragment (4 halves) per thread, 64-row blocks.
// idx: [n64:6][kb:7][nt8:3][ks:1][lane:5]  -> 4,194,304 threads (16384 blocks!)
__global__ void __launch_bounds__(256) prep_b(const float* __restrict__ src,
                                              uint2* __restrict__ dst) {
    const int idx  = blockIdx.x * 256 + threadIdx.x;
    const int lane = idx & 31;
    const int ks   = (idx >> 5) & 1;
    const int nt8  = (idx >> 6) & 7;
    const int kb   = (idx >> 9) & 127;
    const int n64  = idx >> 16;
    const int n = n64 * 64 + nt8 * 8 + (lane >> 2);
    const int k = kb * 32 + ks * 16 + (lane & 3) * 2;
    const float* p = src + (size_t)n * KDIM + k;
    const float2 v0 = *reinterpret_cast<const float2*>(p);
    const float2 v1 = *reinterpret_cast<const float2*>(p + 8);
    uint2 o;
    o.x = pack_h2(v0.x, v0.y);
    o.y = pack_h2(v1.x, v1.y);
    dst[idx] = o;
}

// ---------------------------------------------------------------------------
// GEMM: 64 threads = 2 warps, each a 64x64 warp tile. 2 CTA/SM.
// 8-stage bulk-copy pipeline, mbarrier-only synchronization.
// ---------------------------------------------------------------------------
__global__ void __launch_bounds__(64, 2) gemm_f16_mma(
    const __half* __restrict__ Ap,
    const __half* __restrict__ Bp,
    const float* __restrict__ bias,
    float* __restrict__ out)
{
    extern __shared__ char smem[];
    const uint32_t sb = smem_u32(smem);
    const int tid  = threadIdx.x;
    const int lane = tid & 31;
    const int warp = tid >> 5;          // 0,1 -> M halves

    const int m128 = blockIdx.x & 31;   // M fastest (L2 reuse of B)
    const int n64  = blockIdx.x >> 5;

    // barriers: full[s] at sb + s*8, empty[s] at sb + 64 + s*8
    const uint32_t FULL0  = sb;
    const uint32_t EMPTY0 = sb + 64;
    const uint32_t DATA0  = sb + SMEM_DATA;

    if (tid == 0) {
        #pragma unroll
        for (int s = 0; s < STAGES; s++) {
            mbar_init(FULL0 + s * 8, 1);
            mbar_init(EMPTY0 + s * 8, 64);
        }
    }
    __syncthreads();

    // Contiguous fragment blocks in gmem.
    const char* gA = (const char*)Ap + (size_t)m128 * (128 * KDIM * 2);  // +kf*8192
    const char* gB = (const char*)Bp + (size_t)n64  * (64  * KDIM * 2);  // +kf*4096

    // ---- prologue: fill stages 0..6 ----
    if (tid == 0) {
        #pragma unroll
        for (int s = 0; s < STAGES - 1; s++) {
            const uint32_t f = FULL0 + s * 8;
            mbar_expect_tx(f, STG);
            bulk_ld(DATA0 + s * STG,         gA + (size_t)s * A_STG, A_STG, f);
            bulk_ld(DATA0 + s * STG + A_STG, gB + (size_t)s * B_STG, B_STG, f);
        }
    }

    // Fragment bases.
    const uint32_t aBase = DATA0 + (uint32_t)warp * 4096 + lane * 16;  // + mt*1024 + ks*512
    const uint32_t bBase = DATA0 + A_STG + lane * 8;                    // + nt*512 + ks*256

    float acc[4][8][4];
    #pragma unroll
    for (int i = 0; i < 4; i++)
        #pragma unroll
        for (int j = 0; j < 8; j++)
            #pragma unroll
            for (int r = 0; r < 4; r++) acc[i][j][r] = 0.f;

    // ---- mainloop: mbarrier-only ----
    #pragma unroll 1
    for (int k = 0; k < K_ITERS; k++) {
        const int s = k & (STAGES - 1);

        // producer: refill stage (k+7) after its previous consumers release it
        if (tid == 0 && k + STAGES - 1 < K_ITERS) {
            const int kf = k + STAGES - 1;
            const int sf = kf & (STAGES - 1);
            mbar_wait(EMPTY0 + sf * 8, ((kf >> 3) + 1) & 1);
            const uint32_t f = FULL0 + sf * 8;
            mbar_expect_tx(f, STG);
            bulk_ld(DATA0 + sf * STG,         gA + (size_t)kf * A_STG, A_STG, f);
            bulk_ld(DATA0 + sf * STG + A_STG, gB + (size_t)kf * B_STG, B_STG, f);
        }

        mbar_wait(FULL0 + s * 8, (k >> 3) & 1);

        const uint32_t ab = aBase + s * STG;
        const uint32_t bb = bBase + s * STG;

        uint32_t afr[2][4][4];
        uint32_t bfr[2][8][2];
        #pragma unroll
        for (int ks = 0; ks < 2; ks++) {
            #pragma unroll
            for (int mt = 0; mt < 4; mt++)
                lds128(afr[ks][mt], ab + mt * 1024 + ks * 512);
            #pragma unroll
            for (int nt = 0; nt < 8; nt++)
                lds64(bfr[ks][nt], bb + nt * 512 + ks * 256);
        }

        // release stage (all 64 threads arrive; regs now hold the data)
        mbar_arrive(EMPTY0 + s * 8);

        #pragma unroll
        for (int ks = 0; ks < 2; ks++)
            #pragma unroll
            for (int mt = 0; mt < 4; mt++)
                #pragma unroll
                for (int nt = 0; nt < 8; nt++)
                    mma_f16(acc[mt][nt], afr[ks][mt], bfr[ks][nt]);
    }

    // ---- epilogue: bias + float2 stores ----
    const int fr = lane >> 2;
    const int orow0 = m128 * 128 + warp * 64 + fr;
    const int ocol0 = n64 * 64 + 2 * (lane & 3);

    float2 bv[8];
    #pragma unroll
    for (int nt = 0; nt < 8; nt++)
        bv[nt] = *reinterpret_cast<const float2*>(bias + ocol0 + nt * 8);

    #pragma unroll
    for (int mt = 0; mt < 4; mt++) {
        const int r0 = orow0 + mt * 16;
        #pragma unroll
        for (int nt = 0; nt < 8; nt++) {
            const int col = ocol0 + nt * 8;
            float2 v0 = { acc[mt][nt][0] + bv[nt].x, acc[mt][nt][1] + bv[nt].y };
            float2 v1 = { acc[mt][nt][2] + bv[nt].x, acc[mt][nt][3] + bv[nt].y };
            *reinterpret_cast<float2*>(out + (size_t)r0 * KDIM + col) = v0;
            *reinterpret_cast<float2*>(out + (size_t)(r0 + 8) * KDIM + col) = v1;
        }
    }
}

// ---------------------------------------------------------------------------
extern "C" void kernel_launch(void* const* d_in, const int* in_sizes, int n_in,
                              void* d_out, int out_size) {
    const float* x    = (const float*)d_in[0];
    const float* w    = (const float*)d_in[1];
    const float* bias = (const float*)d_in[2];
    float* out        = (float*)d_out;

    void* gx = nullptr;
    void* gw = nullptr;
    cudaGetSymbolAddress(&gx, g_xa);
    cudaGetSymbolAddress(&gw, g_wb);

    static bool attr_set = false;  // host-side only
    if (!attr_set) {
        cudaFuncSetAttribute(gemm_f16_mma,
                             cudaFuncAttributeMaxDynamicSharedMemorySize, SMEM_TOTAL);
        attr_set = true;
    }

    prep_a<<<8192, 256>>>(x, (uint4*)gx);
    prep_b<<<16384, 256>>>(w, (uint2*)gw);   // 4,194,304 fragments (FIXED)

    // 32 M-tiles x 64 N-tiles = 2048 CTAs of 128x64, 2/SM.
    gemm_f16_mma<<<2048, 64, SMEM_TOTAL>>>((const __half*)gx, (const __half*)gw,
                                           bias, out);
}

// round 8
// speedup vs baseline: 1.3990x; 1.3990x over previous
#include <cuda_runtime.h>
#include <cuda_fp16.h>
#include <cstdint>

// ============================================================================
// y = x @ W^T + b (4096^3 fp32), mma.sync.m16n8k16.f32.f16.f16.f32.
//
// Round-8: round-4 structure (128-thread CTA, 2 CTA/SM, per-thread cp.async,
// per-iter __syncthreads, 4-stage pipeline) with:
//   * CTA tile 128x64  -> 2048 CTAs: wave quantization 6.92->7 (x1.012,
//     was 3.46->4 = x1.156 at 1024 CTAs).
//   * BK=64 -> per-k-iter MMA window per SMSP stays 1024 cyc (same barrier
//     amortization as round 4), 64 k-iters total.
// Warp tile 64x32 (4 warps: 2 wm x 2 wn). Stage = 16KB A + 8KB B = 24KB,
// 4 stages = 96KB, 2 CTA/SM = 192KB smem.
//
// Pre-pass converts fp32->fp16 (RN) into exact mma fragment order:
//   A'[m128][kb128][mt16:8][ks:2][lane:32][4xb32]   (8KB per (m128,kb))
//   B'[n64 ][kb128][nt8:8 ][ks:2][lane:32][2xb32]   (4KB per (n64,kb))
// BK=64 consumes two consecutive kb blocks per iteration (still contiguous).
// ============================================================================

#define KDIM 4096
#define BK 64
#define STAGES 4
#define K_ITERS (KDIM / BK)               // 64
#define A_STG 16384                       // 128 x 64 x 2B
#define B_STG 8192                        // 64 x 64 x 2B
#define STG (A_STG + B_STG)               // 24576
#define SMEM_TOTAL (STAGES * STG)         // 98304

__device__ __half g_xa[(size_t)KDIM * KDIM];   // A' fragment-ordered fp16
__device__ __half g_wb[(size_t)KDIM * KDIM];   // B' fragment-ordered fp16

// ---------------------------------------------------------------------------
__device__ __forceinline__ uint32_t smem_u32(const void* p) {
    uint32_t a;
    asm("{ .reg .u64 t; cvta.to.shared.u64 t, %1; cvt.u32.u64 %0, t; }"
        : "=r"(a) : "l"(p));
    return a;
}
__device__ __forceinline__ void cp_async16(uint32_t dst, const void* src) {
    asm volatile("cp.async.cg.shared.global [%0], [%1], 16;"
                 :: "r"(dst), "l"(src) : "memory");
}
__device__ __forceinline__ void cp_commit() {
    asm volatile("cp.async.commit_group;" ::: "memory");
}
__device__ __forceinline__ void cp_wait2() {
    asm volatile("cp.async.wait_group 2;" ::: "memory");
}
__device__ __forceinline__ void lds128(uint32_t* r, uint32_t a) {
    asm volatile("ld.shared.v4.b32 {%0,%1,%2,%3}, [%4];"
                 : "=r"(r[0]), "=r"(r[1]), "=r"(r[2]), "=r"(r[3]) : "r"(a));
}
__device__ __forceinline__ void lds64(uint32_t* r, uint32_t a) {
    asm volatile("ld.shared.v2.b32 {%0,%1}, [%2];"
                 : "=r"(r[0]), "=r"(r[1]) : "r"(a));
}
__device__ __forceinline__ void mma_f16(float* c, const uint32_t* a, const uint32_t* b) {
    asm volatile(
        "mma.sync.aligned.m16n8k16.row.col.f32.f16.f16.f32 "
        "{%0,%1,%2,%3}, {%4,%5,%6,%7}, {%8,%9}, {%0,%1,%2,%3};"
        : "+f"(c[0]), "+f"(c[1]), "+f"(c[2]), "+f"(c[3])
        : "r"(a[0]), "r"(a[1]), "r"(a[2]), "r"(a[3]), "r"(b[0]), "r"(b[1]));
}
__device__ __forceinline__ uint32_t pack_h2(float lo, float hi) {
    __half2 h = __floats2half2_rn(lo, hi);
    return *reinterpret_cast<uint32_t*>(&h);
}

// ---------------------------------------------------------------------------
// Pre-pass A: one 16B fragment (8 halves) per thread.
// idx: [m128:5][kb:7][mt16:3][ks:1][lane:5]  -> 2,097,152 threads
// ---------------------------------------------------------------------------
__global__ void __launch_bounds__(256) prep_a(const float* __restrict__ src,
                                              uint4* __restrict__ dst) {
    const int idx  = blockIdx.x * 256 + threadIdx.x;
    const int lane = idx & 31;
    const int ks   = (idx >> 5) & 1;
    const int mt16 = (idx >> 6) & 7;
    const int kb   = (idx >> 9) & 127;
    const int m128 = idx >> 16;
    const int row = m128 * 128 + mt16 * 16 + (lane >> 2);
    const int col = kb * 32 + ks * 16 + (lane & 3) * 2;
    const float* p = src + (size_t)row * KDIM + col;
    const float2 v00 = *reinterpret_cast<const float2*>(p);
    const float2 v10 = *reinterpret_cast<const float2*>(p + (size_t)8 * KDIM);
    const float2 v01 = *reinterpret_cast<const float2*>(p + 8);
    const float2 v11 = *reinterpret_cast<const float2*>(p + (size_t)8 * KDIM + 8);
    uint4 o;
    o.x = pack_h2(v00.x, v00.y);
    o.y = pack_h2(v10.x, v10.y);
    o.z = pack_h2(v01.x, v01.y);
    o.w = pack_h2(v11.x, v11.y);
    dst[idx] = o;
}

// Pre-pass B: one 8B fragment (4 halves) per thread, 64-row blocks.
// idx: [n64:6][kb:7][nt8:3][ks:1][lane:5]  -> 4,194,304 threads (16384 blocks)
__global__ void __launch_bounds__(256) prep_b(const float* __restrict__ src,
                                              uint2* __restrict__ dst) {
    const int idx  = blockIdx.x * 256 + threadIdx.x;
    const int lane = idx & 31;
    const int ks   = (idx >> 5) & 1;
    const int nt8  = (idx >> 6) & 7;
    const int kb   = (idx >> 9) & 127;
    const int n64  = idx >> 16;
    const int n = n64 * 64 + nt8 * 8 + (lane >> 2);
    const int k = kb * 32 + ks * 16 + (lane & 3) * 2;
    const float* p = src + (size_t)n * KDIM + k;
    const float2 v0 = *reinterpret_cast<const float2*>(p);
    const float2 v1 = *reinterpret_cast<const float2*>(p + 8);
    uint2 o;
    o.x = pack_h2(v0.x, v0.y);
    o.y = pack_h2(v1.x, v1.y);
    dst[idx] = o;
}

// ---------------------------------------------------------------------------
// GEMM: 128 threads, 4 warps (2 wm x 2 wn of 64x32 warp tiles), 2 CTA/SM.
// ---------------------------------------------------------------------------
__global__ void __launch_bounds__(128, 2) gemm_f16_mma(
    const __half* __restrict__ Ap,
    const __half* __restrict__ Bp,
    const float* __restrict__ bias,
    float* __restrict__ out)
{
    extern __shared__ char smem[];
    const uint32_t sb = smem_u32(smem);

    const int tid  = threadIdx.x;
    const int lane = tid & 31;
    const int warp = tid >> 5;
    const int wm   = warp & 1;     // 2 warp rows (64 each)
    const int wn   = warp >> 1;    // 2 warp cols (32 each)

    const int m128 = blockIdx.x & 31;   // M fastest (B-tile L2 reuse)
    const int n64  = blockIdx.x >> 5;

    // Contiguous fragment blocks. Per BK=64 iter: A 16KB, B 8KB, linear.
    const char* gA = (const char*)Ap + (size_t)m128 * (128 * KDIM * 2) + tid * 16;
    const char* gB = (const char*)Bp + (size_t)n64  * (64  * KDIM * 2) + tid * 16;

    // Fragment bases within a stage (half h = ks>>1 adds 8192 / 4096).
    const uint32_t aFragBase = sb + (uint32_t)(wm * 4) * 1024 + lane * 16;
    const uint32_t bFragBase = sb + A_STG + (uint32_t)(wn * 4) * 512 + lane * 8;

    float acc[4][4][4];
    #pragma unroll
    for (int i = 0; i < 4; i++)
        #pragma unroll
        for (int j = 0; j < 4; j++)
            #pragma unroll
            for (int r = 0; r < 4; r++) acc[i][j][r] = 0.f;

    // ---- prologue: fill stages 0..2 (8 A + 4 B chunks of 16B per thread) ----
    #pragma unroll
    for (int s = 0; s < STAGES - 1; s++) {
        const uint32_t d = sb + s * STG + tid * 16;
        const char* srcA = gA + (size_t)s * A_STG;
        const char* srcB = gB + (size_t)s * B_STG;
        #pragma unroll
        for (int i = 0; i < 8; i++)
            cp_async16(d + i * 2048, srcA + i * 2048);
        #pragma unroll
        for (int i = 0; i < 4; i++)
            cp_async16(d + A_STG + i * 2048, srcB + i * 2048);
        cp_commit();
    }

    // ---- mainloop ----
    #pragma unroll 1
    for (int k = 0; k < K_ITERS; k++) {
        cp_wait2();
        __syncthreads();

        if (k + STAGES - 1 < K_ITERS) {
            const int kf = k + STAGES - 1;
            const uint32_t d = sb + (kf & (STAGES - 1)) * STG + tid * 16;
            const char* srcA = gA + (size_t)kf * A_STG;
            const char* srcB = gB + (size_t)kf * B_STG;
            #pragma unroll
            for (int i = 0; i < 8; i++)
                cp_async16(d + i * 2048, srcA + i * 2048);
            #pragma unroll
            for (int i = 0; i < 4; i++)
                cp_async16(d + A_STG + i * 2048, srcB + i * 2048);
        }
        cp_commit();

        const uint32_t st = (uint32_t)(k & (STAGES - 1)) * STG;
        const uint32_t ab = aFragBase + st;
        const uint32_t bb = bFragBase + st;

        #pragma unroll
        for (int ks = 0; ks < 4; ks++) {
            const uint32_t ah = ab + (ks >> 1) * 8192 + (ks & 1) * 512;
            const uint32_t bh = bb + (ks >> 1) * 4096 + (ks & 1) * 256;
            uint32_t afr[4][4];
            uint32_t bfr[4][2];
            #pragma unroll
            for (int mt = 0; mt < 4; mt++)
                lds128(afr[mt], ah + mt * 1024);
            #pragma unroll
            for (int nt = 0; nt < 4; nt++)
                lds64(bfr[nt], bh + nt * 512);
            #pragma unroll
            for (int mt = 0; mt < 4; mt++)
                #pragma unroll
                for (int nt = 0; nt < 4; nt++)
                    mma_f16(acc[mt][nt], afr[mt], bfr[nt]);
        }
    }

    // ---- epilogue: bias + float2 stores ----
    const int fr = lane >> 2;
    const int orow0 = m128 * 128 + wm * 64 + fr;
    const int ocol0 = n64 * 64 + wn * 32 + 2 * (lane & 3);

    float2 bv[4];
    #pragma unroll
    for (int nt = 0; nt < 4; nt++)
        bv[nt] = *reinterpret_cast<const float2*>(bias + ocol0 + nt * 8);

    #pragma unroll
    for (int mt = 0; mt < 4; mt++) {
        const int r0 = orow0 + mt * 16;
        #pragma unroll
        for (int nt = 0; nt < 4; nt++) {
            const int col = ocol0 + nt * 8;
            float2 v0 = { acc[mt][nt][0] + bv[nt].x, acc[mt][nt][1] + bv[nt].y };
            float2 v1 = { acc[mt][nt][2] + bv[nt].x, acc[mt][nt][3] + bv[nt].y };
            *reinterpret_cast<float2*>(out + (size_t)r0 * KDIM + col) = v0;
            *reinterpret_cast<float2*>(out + (size_t)(r0 + 8) * KDIM + col) = v1;
        }
    }
}

// ---------------------------------------------------------------------------
extern "C" void kernel_launch(void* const* d_in, const int* in_sizes, int n_in,
                              void* d_out, int out_size) {
    const float* x    = (const float*)d_in[0];
    const float* w    = (const float*)d_in[1];
    const float* bias = (const float*)d_in[2];
    float* out        = (float*)d_out;

    void* gx = nullptr;
    void* gw = nullptr;
    cudaGetSymbolAddress(&gx, g_xa);
    cudaGetSymbolAddress(&gw, g_wb);

    static bool attr_set = false;  // host-side only
    if (!attr_set) {
        cudaFuncSetAttribute(gemm_f16_mma,
                             cudaFuncAttributeMaxDynamicSharedMemorySize, SMEM_TOTAL);
        attr_set = true;
    }

    prep_a<<<8192, 256>>>(x, (uint4*)gx);
    prep_b<<<16384, 256>>>(w, (uint2*)gw);

    // 32 M-tiles x 64 N-tiles = 2048 CTAs of 128x64, 2/SM.
    gemm_f16_mma<<<2048, 128, SMEM_TOTAL>>>((const __half*)gx, (const __half*)gw,
                                            bias, out);
}

// round 9
// speedup vs baseline: 1.4477x; 1.0348x over previous
#include <cuda_runtime.h>
#include <cuda_fp16.h>
#include <cstdint>

// ============================================================================
// y = x @ W^T + b (4096^3 fp32), mma.sync.m16n8k16.f32.f16.f16.f32.
//
// Round-9: round-4 geometry (CTA tile 128x128, 4 warps of 64x64, 1024 CTAs,
// 2 CTA/SM) -- the best measured traffic/LDS configuration -- with per-iter
// overhead halved:
//   * BK=64 (two 32-k fragment blocks per iter), K_ITERS=64, 3-stage
//     pipeline (32KB/stage, 96KB smem). Half the barriers/waits of round 4.
//   * prep_a/prep_b fused into one kernel (A and B conversion overlap).
//
// Pre-pass converts fp32->fp16 (RN) into exact mma fragment order:
//   A'[m128][kb128][mt16:8][ks:2][lane:32][4xb32]   (8KB per (m128,kb))
//   B'[n128][kb128][nt8:16][ks:2][lane:32][2xb32]   (8KB per (n128,kb))
// ============================================================================

#define KDIM 4096
#define BK 64
#define STAGES 3
#define K_ITERS (KDIM / BK)               // 64
#define A_STG 16384                       // 128 x 64 x 2B
#define B_STG 16384
#define STG (A_STG + B_STG)               // 32768
#define SMEM_TOTAL (STAGES * STG)         // 98304

__device__ __half g_xa[(size_t)KDIM * KDIM];   // A' fragment-ordered fp16
__device__ __half g_wb[(size_t)KDIM * KDIM];   // B' fragment-ordered fp16

// ---------------------------------------------------------------------------
__device__ __forceinline__ uint32_t smem_u32(const void* p) {
    uint32_t a;
    asm("{ .reg .u64 t; cvta.to.shared.u64 t, %1; cvt.u32.u64 %0, t; }"
        : "=r"(a) : "l"(p));
    return a;
}
__device__ __forceinline__ void cp_async16(uint32_t dst, const void* src) {
    asm volatile("cp.async.cg.shared.global [%0], [%1], 16;"
                 :: "r"(dst), "l"(src) : "memory");
}
__device__ __forceinline__ void cp_commit() {
    asm volatile("cp.async.commit_group;" ::: "memory");
}
__device__ __forceinline__ void cp_wait1() {
    asm volatile("cp.async.wait_group 1;" ::: "memory");
}
__device__ __forceinline__ void lds128(uint32_t* r, uint32_t a) {
    asm volatile("ld.shared.v4.b32 {%0,%1,%2,%3}, [%4];"
                 : "=r"(r[0]), "=r"(r[1]), "=r"(r[2]), "=r"(r[3]) : "r"(a));
}
__device__ __forceinline__ void lds64(uint32_t* r, uint32_t a) {
    asm volatile("ld.shared.v2.b32 {%0,%1}, [%2];"
                 : "=r"(r[0]), "=r"(r[1]) : "r"(a));
}
__device__ __forceinline__ void mma_f16(float* c, const uint32_t* a, const uint32_t* b) {
    asm volatile(
        "mma.sync.aligned.m16n8k16.row.col.f32.f16.f16.f32 "
        "{%0,%1,%2,%3}, {%4,%5,%6,%7}, {%8,%9}, {%0,%1,%2,%3};"
        : "+f"(c[0]), "+f"(c[1]), "+f"(c[2]), "+f"(c[3])
        : "r"(a[0]), "r"(a[1]), "r"(a[2]), "r"(a[3]), "r"(b[0]), "r"(b[1]));
}
__device__ __forceinline__ uint32_t pack_h2(float lo, float hi) {
    __half2 h = __floats2half2_rn(lo, hi);
    return *reinterpret_cast<uint32_t*>(&h);
}

// ---------------------------------------------------------------------------
// Fused pre-pass. Blocks [0,8192): A fragments. Blocks [8192,24576): B.
// A idx: [m128:5][kb:7][mt16:3][ks:1][lane:5]  (one 16B frag / thread)
// B idx: [n128:5][kb:7][nt8:4][ks:1][lane:5]   (one 8B frag / thread)
// ---------------------------------------------------------------------------
__global__ void __launch_bounds__(256) prep_ab(const float* __restrict__ xa,
                                               const float* __restrict__ wb,
                                               uint4* __restrict__ da,
                                               uint2* __restrict__ db) {
    const int bid = blockIdx.x;
    if (bid < 8192) {
        const int idx  = bid * 256 + threadIdx.x;
        const int lane = idx & 31;
        const int ks   = (idx >> 5) & 1;
        const int mt16 = (idx >> 6) & 7;
        const int kb   = (idx >> 9) & 127;
        const int m128 = idx >> 16;
        const int row = m128 * 128 + mt16 * 16 + (lane >> 2);
        const int col = kb * 32 + ks * 16 + (lane & 3) * 2;
        const float* p = xa + (size_t)row * KDIM + col;
        const float2 v00 = *reinterpret_cast<const float2*>(p);
        const float2 v10 = *reinterpret_cast<const float2*>(p + (size_t)8 * KDIM);
        const float2 v01 = *reinterpret_cast<const float2*>(p + 8);
        const float2 v11 = *reinterpret_cast<const float2*>(p + (size_t)8 * KDIM + 8);
        uint4 o;
        o.x = pack_h2(v00.x, v00.y);
        o.y = pack_h2(v10.x, v10.y);
        o.z = pack_h2(v01.x, v01.y);
        o.w = pack_h2(v11.x, v11.y);
        da[idx] = o;
    } else {
        const int idx  = (bid - 8192) * 256 + threadIdx.x;
        const int lane = idx & 31;
        const int ks   = (idx >> 5) & 1;
        const int nt8  = (idx >> 6) & 15;
        const int kb   = (idx >> 10) & 127;
        const int n128 = idx >> 17;
        const int n = n128 * 128 + nt8 * 8 + (lane >> 2);
        const int k = kb * 32 + ks * 16 + (lane & 3) * 2;
        const float* p = wb + (size_t)n * KDIM + k;
        const float2 v0 = *reinterpret_cast<const float2*>(p);
        const float2 v1 = *reinterpret_cast<const float2*>(p + 8);
        uint2 o;
        o.x = pack_h2(v0.x, v0.y);
        o.y = pack_h2(v1.x, v1.y);
        db[idx] = o;
    }
}

// ---------------------------------------------------------------------------
// GEMM: 128 threads, 4 warps (2 wm x 2 wn of 64x64 warp tiles), 2 CTA/SM.
// BK=64: each k-iter consumes two consecutive 32-k fragment blocks.
// ---------------------------------------------------------------------------
__global__ void __launch_bounds__(128, 2) gemm_f16_mma(
    const __half* __restrict__ Ap,
    const __half* __restrict__ Bp,
    const float* __restrict__ bias,
    float* __restrict__ out)
{
    extern __shared__ char smem[];
    const uint32_t sb = smem_u32(smem);

    const int tid  = threadIdx.x;
    const int lane = tid & 31;
    const int warp = tid >> 5;
    const int wm   = warp & 1;     // 2 warp rows (64 each)
    const int wn   = warp >> 1;    // 2 warp cols (64 each)

    const int m128 = blockIdx.x & 31;   // M fastest (B-tile L2 reuse)
    const int n128 = blockIdx.x >> 5;

    // Contiguous fragment blocks: 16KB of A + 16KB of B per BK=64 iter.
    const char* gA = (const char*)Ap + (size_t)m128 * (128 * KDIM * 2) + tid * 16;
    const char* gB = (const char*)Bp + (size_t)n128 * (128 * KDIM * 2) + tid * 16;

    // Fragment bases within a stage; kh (0/1) adds 8192 to both.
    const uint32_t aFragBase = sb + (uint32_t)wm * 4096 + lane * 16;          // +mt*1024 +ks*512
    const uint32_t bFragBase = sb + A_STG + (uint32_t)wn * 4096 + lane * 8;   // +nt*512  +ks*256

    float acc[4][8][4];
    #pragma unroll
    for (int i = 0; i < 4; i++)
        #pragma unroll
        for (int j = 0; j < 8; j++)
            #pragma unroll
            for (int r = 0; r < 4; r++) acc[i][j][r] = 0.f;

    // ---- prologue: fill stages 0,1 (8 A + 8 B chunks of 16B per thread) ----
    #pragma unroll
    for (int s = 0; s < STAGES - 1; s++) {
        const uint32_t d = sb + s * STG + tid * 16;
        const char* srcA = gA + (size_t)s * A_STG;
        const char* srcB = gB + (size_t)s * B_STG;
        #pragma unroll
        for (int i = 0; i < 8; i++) {
            cp_async16(d + i * 2048, srcA + i * 2048);
            cp_async16(d + A_STG + i * 2048, srcB + i * 2048);
        }
        cp_commit();
    }

    // ---- mainloop (64 iters) ----
    #pragma unroll 1
    for (int k = 0; k < K_ITERS; k++) {
        cp_wait1();
        __syncthreads();

        if (k + STAGES - 1 < K_ITERS) {
            const int kf = k + STAGES - 1;
            const uint32_t d = sb + (kf % STAGES) * STG + tid * 16;
            const char* srcA = gA + (size_t)kf * A_STG;
            const char* srcB = gB + (size_t)kf * B_STG;
            #pragma unroll
            for (int i = 0; i < 8; i++) {
                cp_async16(d + i * 2048, srcA + i * 2048);
                cp_async16(d + A_STG + i * 2048, srcB + i * 2048);
            }
        }
        cp_commit();

        const uint32_t st = (uint32_t)(k % STAGES) * STG;

        #pragma unroll
        for (int kh = 0; kh < 2; kh++) {          // two 32-k fragment blocks
            const uint32_t ab = aFragBase + st + kh * 8192;
            const uint32_t bb = bFragBase + st + kh * 8192;
            #pragma unroll
            for (int ks = 0; ks < 2; ks++) {
                uint32_t afr[4][4];
                uint32_t bfr[8][2];
                #pragma unroll
                for (int mt = 0; mt < 4; mt++)
                    lds128(afr[mt], ab + mt * 1024 + ks * 512);
                #pragma unroll
                for (int nt = 0; nt < 8; nt++)
                    lds64(bfr[nt], bb + nt * 512 + ks * 256);
                #pragma unroll
                for (int mt = 0; mt < 4; mt++)
                    #pragma unroll
                    for (int nt = 0; nt < 8; nt++)
                        mma_f16(acc[mt][nt], afr[mt], bfr[nt]);
            }
        }
    }

    // ---- epilogue: bias + float2 stores ----
    const int fr = lane >> 2;
    const int orow0 = m128 * 128 + wm * 64 + fr;
    const int ocol0 = n128 * 128 + wn * 64 + 2 * (lane & 3);

    float2 bv[8];
    #pragma unroll
    for (int nt = 0; nt < 8; nt++)
        bv[nt] = *reinterpret_cast<const float2*>(bias + ocol0 + nt * 8);

    #pragma unroll
    for (int mt = 0; mt < 4; mt++) {
        const int r0 = orow0 + mt * 16;
        #pragma unroll
        for (int nt = 0; nt < 8; nt++) {
            const int col = ocol0 + nt * 8;
            float2 v0 = { acc[mt][nt][0] + bv[nt].x, acc[mt][nt][1] + bv[nt].y };
            float2 v1 = { acc[mt][nt][2] + bv[nt].x, acc[mt][nt][3] + bv[nt].y };
            *reinterpret_cast<float2*>(out + (size_t)r0 * KDIM + col) = v0;
            *reinterpret_cast<float2*>(out + (size_t)(r0 + 8) * KDIM + col) = v1;
        }
    }
}

// ---------------------------------------------------------------------------
extern "C" void kernel_launch(void* const* d_in, const int* in_sizes, int n_in,
                              void* d_out, int out_size) {
    const float* x    = (const float*)d_in[0];
    const float* w    = (const float*)d_in[1];
    const float* bias = (const float*)d_in[2];
    float* out        = (float*)d_out;

    void* gx = nullptr;
    void* gw = nullptr;
    cudaGetSymbolAddress(&gx, g_xa);
    cudaGetSymbolAddress(&gw, g_wb);

    static bool attr_set = false;  // host-side only
    if (!attr_set) {
        cudaFuncSetAttribute(gemm_f16_mma,
                             cudaFuncAttributeMaxDynamicSharedMemorySize, SMEM_TOTAL);
        attr_set = true;
    }

    // Fused fragment-order conversion (A blocks 0..8191, B blocks 8192..24575).
    prep_ab<<<24576, 256>>>(x, w, (uint4*)gx, (uint2*)gw);

    // 32 M-tiles x 32 N-tiles = 1024 CTAs of 128x128, 2/SM.
    gemm_f16_mma<<<1024, 128, SMEM_TOTAL>>>((const __half*)gx, (const __half*)gw,
                                            bias, out);
}

// round 10
// speedup vs baseline: 1.5293x; 1.0564x over previous
#include <cuda_runtime.h>
#include <cuda_fp16.h>
#include <cstdint>

// ============================================================================
// y = x @ W^T + b (4096^3 fp32), mma.sync.m16n8k16.f32.f16.f16.f32.
//
// Round-10: round-9 GEMM core (CTA 128x128, 4 warps of 64x64, BK=64,
// 3-stage cp.async, 2 CTA/SM) + HYBRID SPLIT-K TAIL to kill wave
// quantization (1024 tiles / 296 slots = 3.46 -> 4 waves, x1.156):
//   * tiles   0..887 : full-K CTAs (exactly 3 waves of 296)
//   * tiles 888..1023: 2 split-K CTAs each (K halves, 32 iters) -> 272 CTAs
//     forming a final HALF-length wave; partials to fp32 scratch
//   * reduce kernel: out = p0 + p1 + bias for the 136 split tiles (~5us)
// Makespan 4 -> 3.5 waves (98.9% slot utilization). Deterministic.
// ============================================================================

#define KDIM 4096
#define STAGES 3
#define A_STG 16384                       // 128 x 64 x 2B
#define B_STG 16384
#define STG (A_STG + B_STG)               // 32768
#define SMEM_TOTAL (STAGES * STG)         // 98304

#define FULL_TILES 888                    // 3 x 296
#define SPLIT_TILES 136                   // 1024 - 888
#define GRID_GEMM (FULL_TILES + 2 * SPLIT_TILES)   // 1160

__device__ __half g_xa[(size_t)KDIM * KDIM];       // A' fragment-ordered fp16
__device__ __half g_wb[(size_t)KDIM * KDIM];       // B' fragment-ordered fp16
__device__ float  g_part[(size_t)2 * SPLIT_TILES * 128 * 128];  // 17.8 MB

// ---------------------------------------------------------------------------
__device__ __forceinline__ uint32_t smem_u32(const void* p) {
    uint32_t a;
    asm("{ .reg .u64 t; cvta.to.shared.u64 t, %1; cvt.u32.u64 %0, t; }"
        : "=r"(a) : "l"(p));
    return a;
}
__device__ __forceinline__ void cp_async16(uint32_t dst, const void* src) {
    asm volatile("cp.async.cg.shared.global [%0], [%1], 16;"
                 :: "r"(dst), "l"(src) : "memory");
}
__device__ __forceinline__ void cp_commit() {
    asm volatile("cp.async.commit_group;" ::: "memory");
}
__device__ __forceinline__ void cp_wait1() {
    asm volatile("cp.async.wait_group 1;" ::: "memory");
}
__device__ __forceinline__ void lds128(uint32_t* r, uint32_t a) {
    asm volatile("ld.shared.v4.b32 {%0,%1,%2,%3}, [%4];"
                 : "=r"(r[0]), "=r"(r[1]), "=r"(r[2]), "=r"(r[3]) : "r"(a));
}
__device__ __forceinline__ void lds64(uint32_t* r, uint32_t a) {
    asm volatile("ld.shared.v2.b32 {%0,%1}, [%2];"
                 : "=r"(r[0]), "=r"(r[1]) : "r"(a));
}
__device__ __forceinline__ void mma_f16(float* c, const uint32_t* a, const uint32_t* b) {
    asm volatile(
        "mma.sync.aligned.m16n8k16.row.col.f32.f16.f16.f32 "
        "{%0,%1,%2,%3}, {%4,%5,%6,%7}, {%8,%9}, {%0,%1,%2,%3};"
        : "+f"(c[0]), "+f"(c[1]), "+f"(c[2]), "+f"(c[3])
        : "r"(a[0]), "r"(a[1]), "r"(a[2]), "r"(a[3]), "r"(b[0]), "r"(b[1]));
}
__device__ __forceinline__ uint32_t pack_h2(float lo, float hi) {
    __half2 h = __floats2half2_rn(lo, hi);
    return *reinterpret_cast<uint32_t*>(&h);
}

// ---------------------------------------------------------------------------
// Fused pre-pass. Blocks [0,8192): A fragments. Blocks [8192,24576): B.
// A idx: [m128:5][kb:7][mt16:3][ks:1][lane:5]  (one 16B frag / thread)
// B idx: [n128:5][kb:7][nt8:4][ks:1][lane:5]   (one 8B frag / thread)
// ---------------------------------------------------------------------------
__global__ void __launch_bounds__(256) prep_ab(const float* __restrict__ xa,
                                               const float* __restrict__ wb,
                                               uint4* __restrict__ da,
                                               uint2* __restrict__ db) {
    const int bid = blockIdx.x;
    if (bid < 8192) {
        const int idx  = bid * 256 + threadIdx.x;
        const int lane = idx & 31;
        const int ks   = (idx >> 5) & 1;
        const int mt16 = (idx >> 6) & 7;
        const int kb   = (idx >> 9) & 127;
        const int m128 = idx >> 16;
        const int row = m128 * 128 + mt16 * 16 + (lane >> 2);
        const int col = kb * 32 + ks * 16 + (lane & 3) * 2;
        const float* p = xa + (size_t)row * KDIM + col;
        const float2 v00 = *reinterpret_cast<const float2*>(p);
        const float2 v10 = *reinterpret_cast<const float2*>(p + (size_t)8 * KDIM);
        const float2 v01 = *reinterpret_cast<const float2*>(p + 8);
        const float2 v11 = *reinterpret_cast<const float2*>(p + (size_t)8 * KDIM + 8);
        uint4 o;
        o.x = pack_h2(v00.x, v00.y);
        o.y = pack_h2(v10.x, v10.y);
        o.z = pack_h2(v01.x, v01.y);
        o.w = pack_h2(v11.x, v11.y);
        da[idx] = o;
    } else {
        const int idx  = (bid - 8192) * 256 + threadIdx.x;
        const int lane = idx & 31;
        const int ks   = (idx >> 5) & 1;
        const int nt8  = (idx >> 6) & 15;
        const int kb   = (idx >> 10) & 127;
        const int n128 = idx >> 17;
        const int n = n128 * 128 + nt8 * 8 + (lane >> 2);
        const int k = kb * 32 + ks * 16 + (lane & 3) * 2;
        const float* p = wb + (size_t)n * KDIM + k;
        const float2 v0 = *reinterpret_cast<const float2*>(p);
        const float2 v1 = *reinterpret_cast<const float2*>(p + 8);
        uint2 o;
        o.x = pack_h2(v0.x, v0.y);
        o.y = pack_h2(v1.x, v1.y);
        db[idx] = o;
    }
}

// ---------------------------------------------------------------------------
// GEMM: 128 threads, 4 warps (2 wm x 2 wn of 64x64 warp tiles), 2 CTA/SM.
// bid < 888: full tile (64 k-iters, bias epilogue to out).
// bid >= 888: split-K half (32 k-iters, raw partial to g_part).
// ---------------------------------------------------------------------------
__global__ void __launch_bounds__(128, 2) gemm_f16_mma(
    const __half* __restrict__ Ap,
    const __half* __restrict__ Bp,
    const float* __restrict__ bias,
    float* __restrict__ out,
    float* __restrict__ part)
{
    extern __shared__ char smem[];
    const uint32_t sb = smem_u32(smem);

    const int tid  = threadIdx.x;
    const int lane = tid & 31;
    const int warp = tid >> 5;
    const int wm   = warp & 1;     // 2 warp rows (64 each)
    const int wn   = warp >> 1;    // 2 warp cols (64 each)

    const int bid = blockIdx.x;
    int t, k0, kiters;
    if (bid < FULL_TILES) { t = bid; k0 = 0; kiters = 64; }
    else {
        const int j = bid - FULL_TILES;
        t = FULL_TILES + (j >> 1);
        k0 = (j & 1) * 32;
        kiters = 32;
    }
    const int m128 = t & 31;            // M fastest (B-tile L2 reuse)
    const int n128 = t >> 5;

    // Contiguous fragment blocks: 16KB of A + 16KB of B per BK=64 iter.
    const char* gA = (const char*)Ap + (size_t)m128 * (128 * KDIM * 2)
                                     + (size_t)k0 * A_STG + tid * 16;
    const char* gB = (const char*)Bp + (size_t)n128 * (128 * KDIM * 2)
                                     + (size_t)k0 * B_STG + tid * 16;

    // Fragment bases within a stage; kh (0/1) adds 8192 to both.
    const uint32_t aFragBase = sb + (uint32_t)wm * 4096 + lane * 16;
    const uint32_t bFragBase = sb + A_STG + (uint32_t)wn * 4096 + lane * 8;

    float acc[4][8][4];
    #pragma unroll
    for (int i = 0; i < 4; i++)
        #pragma unroll
        for (int j = 0; j < 8; j++)
            #pragma unroll
            for (int r = 0; r < 4; r++) acc[i][j][r] = 0.f;

    // ---- prologue: fill stages 0,1 ----
    #pragma unroll
    for (int s = 0; s < STAGES - 1; s++) {
        const uint32_t d = sb + s * STG + tid * 16;
        const char* srcA = gA + (size_t)s * A_STG;
        const char* srcB = gB + (size_t)s * B_STG;
        #pragma unroll
        for (int i = 0; i < 8; i++) {
            cp_async16(d + i * 2048, srcA + i * 2048);
            cp_async16(d + A_STG + i * 2048, srcB + i * 2048);
        }
        cp_commit();
    }

    // ---- mainloop ----
    #pragma unroll 1
    for (int k = 0; k < kiters; k++) {
        cp_wait1();
        __syncthreads();

        if (k + STAGES - 1 < kiters) {
            const int kf = k + STAGES - 1;
            const uint32_t d = sb + (kf % STAGES) * STG + tid * 16;
            const char* srcA = gA + (size_t)kf * A_STG;
            const char* srcB = gB + (size_t)kf * B_STG;
            #pragma unroll
            for (int i = 0; i < 8; i++) {
                cp_async16(d + i * 2048, srcA + i * 2048);
                cp_async16(d + A_STG + i * 2048, srcB + i * 2048);
            }
        }
        cp_commit();

        const uint32_t st = (uint32_t)(k % STAGES) * STG;

        #pragma unroll
        for (int kh = 0; kh < 2; kh++) {
            const uint32_t ab = aFragBase + st + kh * 8192;
            const uint32_t bb = bFragBase + st + kh * 8192;
            #pragma unroll
            for (int ks = 0; ks < 2; ks++) {
                uint32_t afr[4][4];
                uint32_t bfr[8][2];
                #pragma unroll
                for (int mt = 0; mt < 4; mt++)
                    lds128(afr[mt], ab + mt * 1024 + ks * 512);
                #pragma unroll
                for (int nt = 0; nt < 8; nt++)
                    lds64(bfr[nt], bb + nt * 512 + ks * 256);
                #pragma unroll
                for (int mt = 0; mt < 4; mt++)
                    #pragma unroll
                    for (int nt = 0; nt < 8; nt++)
                        mma_f16(acc[mt][nt], afr[mt], bfr[nt]);
            }
        }
    }

    // ---- epilogue ----
    const int fr = lane >> 2;
    const int lrow0 = wm * 64 + fr;                 // 0..127 within tile
    const int lcol0 = wn * 64 + 2 * (lane & 3);     // 0..127 within tile

    if (bid < FULL_TILES) {
        const int orow0 = m128 * 128 + lrow0;
        const int ocol0 = n128 * 128 + lcol0;
        float2 bv[8];
        #pragma unroll
        for (int nt = 0; nt < 8; nt++)
            bv[nt] = *reinterpret_cast<const float2*>(bias + ocol0 + nt * 8);
        #pragma unroll
        for (int mt = 0; mt < 4; mt++) {
            const int r0 = orow0 + mt * 16;
            #pragma unroll
            for (int nt = 0; nt < 8; nt++) {
                const int col = ocol0 + nt * 8;
                float2 v0 = { acc[mt][nt][0] + bv[nt].x, acc[mt][nt][1] + bv[nt].y };
                float2 v1 = { acc[mt][nt][2] + bv[nt].x, acc[mt][nt][3] + bv[nt].y };
                *reinterpret_cast<float2*>(out + (size_t)r0 * KDIM + col) = v0;
                *reinterpret_cast<float2*>(out + (size_t)(r0 + 8) * KDIM + col) = v1;
            }
        }
    } else {
        // raw partial -> part[(bid-888)][128][128]
        float* pt = part + (size_t)(bid - FULL_TILES) * (128 * 128);
        #pragma unroll
        for (int mt = 0; mt < 4; mt++) {
            const int r0 = lrow0 + mt * 16;
            #pragma unroll
            for (int nt = 0; nt < 8; nt++) {
                const int col = lcol0 + nt * 8;
                float2 v0 = { acc[mt][nt][0], acc[mt][nt][1] };
                float2 v1 = { acc[mt][nt][2], acc[mt][nt][3] };
                *reinterpret_cast<float2*>(pt + r0 * 128 + col) = v0;
                *reinterpret_cast<float2*>(pt + (r0 + 8) * 128 + col) = v1;
            }
        }
    }
}

// ---------------------------------------------------------------------------
// Reduce: out(tile 888+j) = part[2j] + part[2j+1] + bias.
// 136 tiles x 4096 float4 = 557,056 float4 -> 2176 blocks x 256 threads.
// ---------------------------------------------------------------------------
__global__ void __launch_bounds__(256) reduce_split(const float* __restrict__ part,
                                                    const float* __restrict__ bias,
                                                    float* __restrict__ out) {
    const int idx = blockIdx.x * 256 + threadIdx.x;     // float4 index
    const int j   = idx >> 12;                          // tile 0..135
    const int e   = idx & 4095;                         // float4 within tile
    const int r   = e >> 5;                             // row 0..127
    const int c   = (e & 31) * 4;                       // col 0..124
    const int t   = FULL_TILES + j;
    const int orow = (t & 31) * 128 + r;
    const int ocol = (t >> 5) * 128 + c;

    const float4 p0 = *reinterpret_cast<const float4*>(
        part + ((size_t)(2 * j) * 16384 + r * 128 + c));
    const float4 p1 = *reinterpret_cast<const float4*>(
        part + ((size_t)(2 * j + 1) * 16384 + r * 128 + c));
    const float4 bv = *reinterpret_cast<const float4*>(bias + ocol);
    float4 o;
    o.x = p0.x + p1.x + bv.x;
    o.y = p0.y + p1.y + bv.y;
    o.z = p0.z + p1.z + bv.z;
    o.w = p0.w + p1.w + bv.w;
    *reinterpret_cast<float4*>(out + (size_t)orow * KDIM + ocol) = o;
}

// ---------------------------------------------------------------------------
extern "C" void kernel_launch(void* const* d_in, const int* in_sizes, int n_in,
                              void* d_out, int out_size) {
    const float* x    = (const float*)d_in[0];
    const float* w    = (const float*)d_in[1];
    const float* bias = (const float*)d_in[2];
    float* out        = (float*)d_out;

    void* gx = nullptr;
    void* gw = nullptr;
    void* gp = nullptr;
    cudaGetSymbolAddress(&gx, g_xa);
    cudaGetSymbolAddress(&gw, g_wb);
    cudaGetSymbolAddress(&gp, g_part);

    static bool attr_set = false;  // host-side only
    if (!attr_set) {
        cudaFuncSetAttribute(gemm_f16_mma,
                             cudaFuncAttributeMaxDynamicSharedMemorySize, SMEM_TOTAL);
        attr_set = true;
    }

    prep_ab<<<24576, 256>>>(x, w, (uint4*)gx, (uint2*)gw);

    gemm_f16_mma<<<GRID_GEMM, 128, SMEM_TOTAL>>>(
        (const __half*)gx, (const __half*)gw, bias, out, (float*)gp);

    reduce_split<<<2176, 256>>>((const float*)gp, bias, out);
}

// round 11
// speedup vs baseline: 1.6267x; 1.0637x over previous
#include <cuda_runtime.h>
#include <cuda_fp16.h>
#include <cstdint>

// ============================================================================
// y = x @ W^T + b (4096^3 fp32), mma.sync.m16n8k16.f32.f16.f16.f32.
//
// Round-11 = round-10 (CTA 128x128, 4 warps of 64x64, BK=64, 3-stage
// cp.async, 2 CTA/SM, hybrid split-K tail: 888 full + 272 half-K CTAs) plus:
//   * software-pipelined inner loop: fragments for (kh,ks) step s+1 are
//     loaded while step s's 32 MMAs issue; refill cp.asyncs placed after
//     step-0 loads so the tensor pipe starts immediately each k-iter.
//   * prep processes 2 independent fragments per thread (2x MLP, HBM-bound).
// ============================================================================

#define KDIM 4096
#define STAGES 3
#define A_STG 16384                       // 128 x 64 x 2B
#define B_STG 16384
#define STG (A_STG + B_STG)               // 32768
#define SMEM_TOTAL (STAGES * STG)         // 98304

#define FULL_TILES 888                    // 3 x 296
#define SPLIT_TILES 136                   // 1024 - 888
#define GRID_GEMM (FULL_TILES + 2 * SPLIT_TILES)   // 1160

__device__ __half g_xa[(size_t)KDIM * KDIM];       // A' fragment-ordered fp16
__device__ __half g_wb[(size_t)KDIM * KDIM];       // B' fragment-ordered fp16
__device__ float  g_part[(size_t)2 * SPLIT_TILES * 128 * 128];  // 17.8 MB

// ---------------------------------------------------------------------------
__device__ __forceinline__ uint32_t smem_u32(const void* p) {
    uint32_t a;
    asm("{ .reg .u64 t; cvta.to.shared.u64 t, %1; cvt.u32.u64 %0, t; }"
        : "=r"(a) : "l"(p));
    return a;
}
__device__ __forceinline__ void cp_async16(uint32_t dst, const void* src) {
    asm volatile("cp.async.cg.shared.global [%0], [%1], 16;"
                 :: "r"(dst), "l"(src) : "memory");
}
__device__ __forceinline__ void cp_commit() {
    asm volatile("cp.async.commit_group;" ::: "memory");
}
__device__ __forceinline__ void cp_wait1() {
    asm volatile("cp.async.wait_group 1;" ::: "memory");
}
__device__ __forceinline__ void lds128(uint32_t* r, uint32_t a) {
    asm volatile("ld.shared.v4.b32 {%0,%1,%2,%3}, [%4];"
                 : "=r"(r[0]), "=r"(r[1]), "=r"(r[2]), "=r"(r[3]) : "r"(a));
}
__device__ __forceinline__ void lds64(uint32_t* r, uint32_t a) {
    asm volatile("ld.shared.v2.b32 {%0,%1}, [%2];"
                 : "=r"(r[0]), "=r"(r[1]) : "r"(a));
}
__device__ __forceinline__ void mma_f16(float* c, const uint32_t* a, const uint32_t* b) {
    asm volatile(
        "mma.sync.aligned.m16n8k16.row.col.f32.f16.f16.f32 "
        "{%0,%1,%2,%3}, {%4,%5,%6,%7}, {%8,%9}, {%0,%1,%2,%3};"
        : "+f"(c[0]), "+f"(c[1]), "+f"(c[2]), "+f"(c[3])
        : "r"(a[0]), "r"(a[1]), "r"(a[2]), "r"(a[3]), "r"(b[0]), "r"(b[1]));
}
__device__ __forceinline__ uint32_t pack_h2(float lo, float hi) {
    __half2 h = __floats2half2_rn(lo, hi);
    return *reinterpret_cast<uint32_t*>(&h);
}

// ---------------------------------------------------------------------------
// Fused pre-pass, 2 fragments per thread (independent addresses -> 2x MLP).
// Blocks [0,4096): A (idx and idx + 2^20). Blocks [4096,12288): B (idx, +2^21).
// A idx: [m128:5][kb:7][mt16:3][ks:1][lane:5]  (16B frag)
// B idx: [n128:5][kb:7][nt8:4][ks:1][lane:5]   (8B frag)
// ---------------------------------------------------------------------------
__device__ __forceinline__ void do_prep_a(const float* __restrict__ xa,
                                          uint4* __restrict__ da, int idx) {
    const int lane = idx & 31;
    const int ks   = (idx >> 5) & 1;
    const int mt16 = (idx >> 6) & 7;
    const int kb   = (idx >> 9) & 127;
    const int m128 = idx >> 16;
    const int row = m128 * 128 + mt16 * 16 + (lane >> 2);
    const int col = kb * 32 + ks * 16 + (lane & 3) * 2;
    const float* p = xa + (size_t)row * KDIM + col;
    const float2 v00 = *reinterpret_cast<const float2*>(p);
    const float2 v10 = *reinterpret_cast<const float2*>(p + (size_t)8 * KDIM);
    const float2 v01 = *reinterpret_cast<const float2*>(p + 8);
    const float2 v11 = *reinterpret_cast<const float2*>(p + (size_t)8 * KDIM + 8);
    uint4 o;
    o.x = pack_h2(v00.x, v00.y);
    o.y = pack_h2(v10.x, v10.y);
    o.z = pack_h2(v01.x, v01.y);
    o.w = pack_h2(v11.x, v11.y);
    da[idx] = o;
}
__device__ __forceinline__ void do_prep_b(const float* __restrict__ wb,
                                          uint2* __restrict__ db, int idx) {
    const int lane = idx & 31;
    const int ks   = (idx >> 5) & 1;
    const int nt8  = (idx >> 6) & 15;
    const int kb   = (idx >> 10) & 127;
    const int n128 = idx >> 17;
    const int n = n128 * 128 + nt8 * 8 + (lane >> 2);
    const int k = kb * 32 + ks * 16 + (lane & 3) * 2;
    const float* p = wb + (size_t)n * KDIM + k;
    const float2 v0 = *reinterpret_cast<const float2*>(p);
    const float2 v1 = *reinterpret_cast<const float2*>(p + 8);
    uint2 o;
    o.x = pack_h2(v0.x, v0.y);
    o.y = pack_h2(v1.x, v1.y);
    db[idx] = o;
}
__global__ void __launch_bounds__(256) prep_ab(const float* __restrict__ xa,
                                               const float* __restrict__ wb,
                                               uint4* __restrict__ da,
                                               uint2* __restrict__ db) {
    const int bid = blockIdx.x;
    if (bid < 4096) {
        const int idx = bid * 256 + threadIdx.x;      // [0, 2^20)
        do_prep_a(xa, da, idx);
        do_prep_a(xa, da, idx + (1 << 20));
    } else {
        const int idx = (bid - 4096) * 256 + threadIdx.x;   // [0, 2^21)
        do_prep_b(wb, db, idx);
        do_prep_b(wb, db, idx + (1 << 21));
    }
}

// ---------------------------------------------------------------------------
// GEMM: 128 threads, 4 warps (2 wm x 2 wn of 64x64 warp tiles), 2 CTA/SM.
// bid < 888: full tile (64 k-iters). bid >= 888: split-K half (32 k-iters).
// Inner loop software-pipelined over the 4 (kh,ks) steps.
// ---------------------------------------------------------------------------
__global__ void __launch_bounds__(128, 2) gemm_f16_mma(
    const __half* __restrict__ Ap,
    const __half* __restrict__ Bp,
    const float* __restrict__ bias,
    float* __restrict__ out,
    float* __restrict__ part)
{
    extern __shared__ char smem[];
    const uint32_t sb = smem_u32(smem);

    const int tid  = threadIdx.x;
    const int lane = tid & 31;
    const int warp = tid >> 5;
    const int wm   = warp & 1;     // 2 warp rows (64 each)
    const int wn   = warp >> 1;    // 2 warp cols (64 each)

    const int bid = blockIdx.x;
    int t, k0, kiters;
    if (bid < FULL_TILES) { t = bid; k0 = 0; kiters = 64; }
    else {
        const int j = bid - FULL_TILES;
        t = FULL_TILES + (j >> 1);
        k0 = (j & 1) * 32;
        kiters = 32;
    }
    const int m128 = t & 31;            // M fastest (B-tile L2 reuse)
    const int n128 = t >> 5;

    const char* gA = (const char*)Ap + (size_t)m128 * (128 * KDIM * 2)
                                     + (size_t)k0 * A_STG + tid * 16;
    const char* gB = (const char*)Bp + (size_t)n128 * (128 * KDIM * 2)
                                     + (size_t)k0 * B_STG + tid * 16;

    const uint32_t aFragBase = sb + (uint32_t)wm * 4096 + lane * 16;
    const uint32_t bFragBase = sb + A_STG + (uint32_t)wn * 4096 + lane * 8;

    float acc[4][8][4];
    #pragma unroll
    for (int i = 0; i < 4; i++)
        #pragma unroll
        for (int j = 0; j < 8; j++)
            #pragma unroll
            for (int r = 0; r < 4; r++) acc[i][j][r] = 0.f;

    // ---- prologue: fill stages 0,1 ----
    #pragma unroll
    for (int s = 0; s < STAGES - 1; s++) {
        const uint32_t d = sb + s * STG + tid * 16;
        const char* srcA = gA + (size_t)s * A_STG;
        const char* srcB = gB + (size_t)s * B_STG;
        #pragma unroll
        for (int i = 0; i < 8; i++) {
            cp_async16(d + i * 2048, srcA + i * 2048);
            cp_async16(d + A_STG + i * 2048, srcB + i * 2048);
        }
        cp_commit();
    }

    // ---- mainloop (software-pipelined steps) ----
    #pragma unroll 1
    for (int k = 0; k < kiters; k++) {
        cp_wait1();
        __syncthreads();

        const uint32_t st = (uint32_t)(k % STAGES) * STG;

        uint32_t afr[2][4][4];
        uint32_t bfr[2][8][2];

        // step 0 loads (kh=0, ks=0)
        #pragma unroll
        for (int mt = 0; mt < 4; mt++)
            lds128(afr[0][mt], aFragBase + st + mt * 1024);
        #pragma unroll
        for (int nt = 0; nt < 8; nt++)
            lds64(bfr[0][nt], bFragBase + st + nt * 512);

        // refill (after step-0 loads so MMAs can start ASAP)
        if (k + STAGES - 1 < kiters) {
            const int kf = k + STAGES - 1;
            const uint32_t d = sb + (kf % STAGES) * STG + tid * 16;
            const char* srcA = gA + (size_t)kf * A_STG;
            const char* srcB = gB + (size_t)kf * B_STG;
            #pragma unroll
            for (int i = 0; i < 8; i++) {
                cp_async16(d + i * 2048, srcA + i * 2048);
                cp_async16(d + A_STG + i * 2048, srcB + i * 2048);
            }
        }
        cp_commit();

        // 4 steps: s = (kh<<1)|ks ; load s+1 before MMAs of s
        #pragma unroll
        for (int s = 0; s < 4; s++) {
            const int cur = s & 1;
            if (s < 3) {
                const int nx  = s + 1;
                const uint32_t ao = (uint32_t)(nx >> 1) * 8192 + (uint32_t)(nx & 1) * 512;
                const uint32_t bo = (uint32_t)(nx >> 1) * 8192 + (uint32_t)(nx & 1) * 256;
                #pragma unroll
                for (int mt = 0; mt < 4; mt++)
                    lds128(afr[cur ^ 1][mt], aFragBase + st + ao + mt * 1024);
                #pragma unroll
                for (int nt = 0; nt < 8; nt++)
                    lds64(bfr[cur ^ 1][nt], bFragBase + st + bo + nt * 512);
            }
            #pragma unroll
            for (int mt = 0; mt < 4; mt++)
                #pragma unroll
                for (int nt = 0; nt < 8; nt++)
                    mma_f16(acc[mt][nt], afr[cur][mt], bfr[cur][nt]);
        }
    }

    // ---- epilogue ----
    const int fr = lane >> 2;
    const int lrow0 = wm * 64 + fr;
    const int lcol0 = wn * 64 + 2 * (lane & 3);

    if (bid < FULL_TILES) {
        const int orow0 = m128 * 128 + lrow0;
        const int ocol0 = n128 * 128 + lcol0;
        float2 bv[8];
        #pragma unroll
        for (int nt = 0; nt < 8; nt++)
            bv[nt] = *reinterpret_cast<const float2*>(bias + ocol0 + nt * 8);
        #pragma unroll
        for (int mt = 0; mt < 4; mt++) {
            const int r0 = orow0 + mt * 16;
            #pragma unroll
            for (int nt = 0; nt < 8; nt++) {
                const int col = ocol0 + nt * 8;
                float2 v0 = { acc[mt][nt][0] + bv[nt].x, acc[mt][nt][1] + bv[nt].y };
                float2 v1 = { acc[mt][nt][2] + bv[nt].x, acc[mt][nt][3] + bv[nt].y };
                *reinterpret_cast<float2*>(out + (size_t)r0 * KDIM + col) = v0;
                *reinterpret_cast<float2*>(out + (size_t)(r0 + 8) * KDIM + col) = v1;
            }
        }
    } else {
        float* pt = part + (size_t)(bid - FULL_TILES) * (128 * 128);
        #pragma unroll
        for (int mt = 0; mt < 4; mt++) {
            const int r0 = lrow0 + mt * 16;
            #pragma unroll
            for (int nt = 0; nt < 8; nt++) {
                const int col = lcol0 + nt * 8;
                float2 v0 = { acc[mt][nt][0], acc[mt][nt][1] };
                float2 v1 = { acc[mt][nt][2], acc[mt][nt][3] };
                *reinterpret_cast<float2*>(pt + r0 * 128 + col) = v0;
                *reinterpret_cast<float2*>(pt + (r0 + 8) * 128 + col) = v1;
            }
        }
    }
}

// ---------------------------------------------------------------------------
// Reduce: out(tile 888+j) = part[2j] + part[2j+1] + bias.
// ---------------------------------------------------------------------------
__global__ void __launch_bounds__(256) reduce_split(const float* __restrict__ part,
                                                    const float* __restrict__ bias,
                                                    float* __restrict__ out) {
    const int idx = blockIdx.x * 256 + threadIdx.x;
    const int j   = idx >> 12;
    const int e   = idx & 4095;
    const int r   = e >> 5;
    const int c   = (e & 31) * 4;
    const int t   = FULL_TILES + j;
    const int orow = (t & 31) * 128 + r;
    const int ocol = (t >> 5) * 128 + c;

    const float4 p0 = *reinterpret_cast<const float4*>(
        part + ((size_t)(2 * j) * 16384 + r * 128 + c));
    const float4 p1 = *reinterpret_cast<const float4*>(
        part + ((size_t)(2 * j + 1) * 16384 + r * 128 + c));
    const float4 bv = *reinterpret_cast<const float4*>(bias + ocol);
    float4 o;
    o.x = p0.x + p1.x + bv.x;
    o.y = p0.y + p1.y + bv.y;
    o.z = p0.z + p1.z + bv.z;
    o.w = p0.w + p1.w + bv.w;
    *reinterpret_cast<float4*>(out + (size_t)orow * KDIM + ocol) = o;
}

// ---------------------------------------------------------------------------
extern "C" void kernel_launch(void* const* d_in, const int* in_sizes, int n_in,
                              void* d_out, int out_size) {
    const float* x    = (const float*)d_in[0];
    const float* w    = (const float*)d_in[1];
    const float* bias = (const float*)d_in[2];
    float* out        = (float*)d_out;

    void* gx = nullptr;
    void* gw = nullptr;
    void* gp = nullptr;
    cudaGetSymbolAddress(&gx, g_xa);
    cudaGetSymbolAddress(&gw, g_wb);
    cudaGetSymbolAddress(&gp, g_part);

    static bool attr_set = false;  // host-side only
    if (!attr_set) {
        cudaFuncSetAttribute(gemm_f16_mma,
                             cudaFuncAttributeMaxDynamicSharedMemorySize, SMEM_TOTAL);
        attr_set = true;
    }

    prep_ab<<<12288, 256>>>(x, w, (uint4*)gx, (uint2*)gw);

    gemm_f16_mma<<<GRID_GEMM, 128, SMEM_TOTAL>>>(
        (const __half*)gx, (const __half*)gw, bias, out, (float*)gp);

    reduce_split<<<2176, 256>>>((const float*)gp, bias, out);
}

// round 12
// speedup vs baseline: 1.6383x; 1.0072x over previous
#include <cuda_runtime.h>
#include <cuda_fp16.h>
#include <cstdint>

// ============================================================================
// y = x @ W^T + b (4096^3 fp32), mma.sync.m16n8k16.f32.f16.f16.f32.
//
// Round-12 = round-11 (CTA 128x128, 4 warps of 64x64, BK=64, 3-stage
// cp.async, 2 CTA/SM, software-pipelined steps, hybrid split-K tail) plus:
//   * prep: 4 independent fragments/thread (MLP 2->4; prep is latency-bound)
//   * GEMM: incremental stage pointers/offsets (no per-iter 64-bit mul or
//     modulo), refill cp.asyncs placed after the first MMA block.
// ============================================================================

#define KDIM 4096
#define STAGES 3
#define A_STG 16384                       // 128 x 64 x 2B
#define B_STG 16384
#define STG (A_STG + B_STG)               // 32768
#define SMEM_TOTAL (STAGES * STG)         // 98304

#define FULL_TILES 888                    // 3 x 296
#define SPLIT_TILES 136                   // 1024 - 888
#define GRID_GEMM (FULL_TILES + 2 * SPLIT_TILES)   // 1160

__device__ __half g_xa[(size_t)KDIM * KDIM];       // A' fragment-ordered fp16
__device__ __half g_wb[(size_t)KDIM * KDIM];       // B' fragment-ordered fp16
__device__ float  g_part[(size_t)2 * SPLIT_TILES * 128 * 128];  // 17.8 MB

// ---------------------------------------------------------------------------
__device__ __forceinline__ uint32_t smem_u32(const void* p) {
    uint32_t a;
    asm("{ .reg .u64 t; cvta.to.shared.u64 t, %1; cvt.u32.u64 %0, t; }"
        : "=r"(a) : "l"(p));
    return a;
}
__device__ __forceinline__ void cp_async16(uint32_t dst, const void* src) {
    asm volatile("cp.async.cg.shared.global [%0], [%1], 16;"
                 :: "r"(dst), "l"(src) : "memory");
}
__device__ __forceinline__ void cp_commit() {
    asm volatile("cp.async.commit_group;" ::: "memory");
}
__device__ __forceinline__ void cp_wait1() {
    asm volatile("cp.async.wait_group 1;" ::: "memory");
}
__device__ __forceinline__ void lds128(uint32_t* r, uint32_t a) {
    asm volatile("ld.shared.v4.b32 {%0,%1,%2,%3}, [%4];"
                 : "=r"(r[0]), "=r"(r[1]), "=r"(r[2]), "=r"(r[3]) : "r"(a));
}
__device__ __forceinline__ void lds64(uint32_t* r, uint32_t a) {
    asm volatile("ld.shared.v2.b32 {%0,%1}, [%2];"
                 : "=r"(r[0]), "=r"(r[1]) : "r"(a));
}
__device__ __forceinline__ void mma_f16(float* c, const uint32_t* a, const uint32_t* b) {
    asm volatile(
        "mma.sync.aligned.m16n8k16.row.col.f32.f16.f16.f32 "
        "{%0,%1,%2,%3}, {%4,%5,%6,%7}, {%8,%9}, {%0,%1,%2,%3};"
        : "+f"(c[0]), "+f"(c[1]), "+f"(c[2]), "+f"(c[3])
        : "r"(a[0]), "r"(a[1]), "r"(a[2]), "r"(a[3]), "r"(b[0]), "r"(b[1]));
}
__device__ __forceinline__ uint32_t pack_h2(float lo, float hi) {
    __half2 h = __floats2half2_rn(lo, hi);
    return *reinterpret_cast<uint32_t*>(&h);
}

// ---------------------------------------------------------------------------
// Fused pre-pass, 4 fragments per thread (independent addresses -> MLP 4).
// Blocks [0,2048): A frags idx + j*2^19, j=0..3   (A space = 2^21)
// Blocks [2048,6144): B frags idx + j*2^20, j=0..3 (B space = 2^22)
// A idx: [m128:5][kb:7][mt16:3][ks:1][lane:5]  (16B frag)
// B idx: [n128:5][kb:7][nt8:4][ks:1][lane:5]   (8B frag)
// ---------------------------------------------------------------------------
__device__ __forceinline__ void do_prep_a(const float* __restrict__ xa,
                                          uint4* __restrict__ da, int idx) {
    const int lane = idx & 31;
    const int ks   = (idx >> 5) & 1;
    const int mt16 = (idx >> 6) & 7;
    const int kb   = (idx >> 9) & 127;
    const int m128 = idx >> 16;
    const int row = m128 * 128 + mt16 * 16 + (lane >> 2);
    const int col = kb * 32 + ks * 16 + (lane & 3) * 2;
    const float* p = xa + (size_t)row * KDIM + col;
    const float2 v00 = *reinterpret_cast<const float2*>(p);
    const float2 v10 = *reinterpret_cast<const float2*>(p + (size_t)8 * KDIM);
    const float2 v01 = *reinterpret_cast<const float2*>(p + 8);
    const float2 v11 = *reinterpret_cast<const float2*>(p + (size_t)8 * KDIM + 8);
    uint4 o;
    o.x = pack_h2(v00.x, v00.y);
    o.y = pack_h2(v10.x, v10.y);
    o.z = pack_h2(v01.x, v01.y);
    o.w = pack_h2(v11.x, v11.y);
    da[idx] = o;
}
__device__ __forceinline__ void do_prep_b(const float* __restrict__ wb,
                                          uint2* __restrict__ db, int idx) {
    const int lane = idx & 31;
    const int ks   = (idx >> 5) & 1;
    const int nt8  = (idx >> 6) & 15;
    const int kb   = (idx >> 10) & 127;
    const int n128 = idx >> 17;
    const int n = n128 * 128 + nt8 * 8 + (lane >> 2);
    const int k = kb * 32 + ks * 16 + (lane & 3) * 2;
    const float* p = wb + (size_t)n * KDIM + k;
    const float2 v0 = *reinterpret_cast<const float2*>(p);
    const float2 v1 = *reinterpret_cast<const float2*>(p + 8);
    uint2 o;
    o.x = pack_h2(v0.x, v0.y);
    o.y = pack_h2(v1.x, v1.y);
    db[idx] = o;
}
__global__ void __launch_bounds__(256) prep_ab(const float* __restrict__ xa,
                                               const float* __restrict__ wb,
                                               uint4* __restrict__ da,
                                               uint2* __restrict__ db) {
    const int bid = blockIdx.x;
    if (bid < 2048) {
        const int idx = bid * 256 + threadIdx.x;            // [0, 2^19)
        #pragma unroll
        for (int j = 0; j < 4; j++)
            do_prep_a(xa, da, idx + j * (1 << 19));
    } else {
        const int idx = (bid - 2048) * 256 + threadIdx.x;   // [0, 2^20)
        #pragma unroll
        for (int j = 0; j < 4; j++)
            do_prep_b(wb, db, idx + j * (1 << 20));
    }
}

// ---------------------------------------------------------------------------
// GEMM: 128 threads, 4 warps (2 wm x 2 wn of 64x64 warp tiles), 2 CTA/SM.
// bid < 888: full tile (64 k-iters). bid >= 888: split-K half (32 k-iters).
// ---------------------------------------------------------------------------
__global__ void __launch_bounds__(128, 2) gemm_f16_mma(
    const __half* __restrict__ Ap,
    const __half* __restrict__ Bp,
    const float* __restrict__ bias,
    float* __restrict__ out,
    float* __restrict__ part)
{
    extern __shared__ char smem[];
    const uint32_t sb = smem_u32(smem);

    const int tid  = threadIdx.x;
    const int lane = tid & 31;
    const int warp = tid >> 5;
    const int wm   = warp & 1;     // 2 warp rows (64 each)
    const int wn   = warp >> 1;    // 2 warp cols (64 each)

    const int bid = blockIdx.x;
    int t, k0, kiters;
    if (bid < FULL_TILES) { t = bid; k0 = 0; kiters = 64; }
    else {
        const int j = bid - FULL_TILES;
        t = FULL_TILES + (j >> 1);
        k0 = (j & 1) * 32;
        kiters = 32;
    }
    const int m128 = t & 31;            // M fastest (B-tile L2 reuse)
    const int n128 = t >> 5;

    const char* gA = (const char*)Ap + (size_t)m128 * (128 * KDIM * 2)
                                     + (size_t)k0 * A_STG + tid * 16;
    const char* gB = (const char*)Bp + (size_t)n128 * (128 * KDIM * 2)
                                     + (size_t)k0 * B_STG + tid * 16;

    const uint32_t aFragBase = sb + (uint32_t)wm * 4096 + lane * 16;
    const uint32_t bFragBase = sb + A_STG + (uint32_t)wn * 4096 + lane * 8;

    float acc[4][8][4];
    #pragma unroll
    for (int i = 0; i < 4; i++)
        #pragma unroll
        for (int j = 0; j < 8; j++)
            #pragma unroll
            for (int r = 0; r < 4; r++) acc[i][j][r] = 0.f;

    // ---- prologue: fill stages 0,1 ----
    #pragma unroll
    for (int s = 0; s < STAGES - 1; s++) {
        const uint32_t d = sb + s * STG + tid * 16;
        const char* srcA = gA + (size_t)s * A_STG;
        const char* srcB = gB + (size_t)s * B_STG;
        #pragma unroll
        for (int i = 0; i < 8; i++) {
            cp_async16(d + i * 2048, srcA + i * 2048);
            cp_async16(d + A_STG + i * 2048, srcB + i * 2048);
        }
        cp_commit();
    }

    // ---- mainloop (incremental pointers; refill after first MMA block) ----
    const char* rA = gA + (size_t)(STAGES - 1) * A_STG;   // fill source, k+2
    const char* rB = gB + (size_t)(STAGES - 1) * B_STG;
    uint32_t st     = 0;                                  // consume stage offset
    uint32_t stFill = (STAGES - 1) * STG;                 // fill stage offset

    #pragma unroll 1
    for (int k = 0; k < kiters; k++) {
        cp_wait1();
        __syncthreads();

        const uint32_t ab = aFragBase + st;
        const uint32_t bb = bFragBase + st;

        uint32_t afr[2][4][4];
        uint32_t bfr[2][8][2];

        // step 0 loads (kh=0, ks=0)
        #pragma unroll
        for (int mt = 0; mt < 4; mt++)
            lds128(afr[0][mt], ab + mt * 1024);
        #pragma unroll
        for (int nt = 0; nt < 8; nt++)
            lds64(bfr[0][nt], bb + nt * 512);

        // step 1 loads, then step-0 MMAs
        #pragma unroll
        for (int mt = 0; mt < 4; mt++)
            lds128(afr[1][mt], ab + 512 + mt * 1024);
        #pragma unroll
        for (int nt = 0; nt < 8; nt++)
            lds64(bfr[1][nt], bb + 256 + nt * 512);
        #pragma unroll
        for (int mt = 0; mt < 4; mt++)
            #pragma unroll
            for (int nt = 0; nt < 8; nt++)
                mma_f16(acc[mt][nt], afr[0][mt], bfr[0][nt]);

        // refill stage k+2 (after first MMA block so tensor starts first)
        if (k + STAGES - 1 < kiters) {
            const uint32_t d = sb + stFill + tid * 16;
            #pragma unroll
            for (int i = 0; i < 8; i++) {
                cp_async16(d + i * 2048, rA + i * 2048);
                cp_async16(d + A_STG + i * 2048, rB + i * 2048);
            }
        }
        cp_commit();

        // step 2 loads, step-1 MMAs
        #pragma unroll
        for (int mt = 0; mt < 4; mt++)
            lds128(afr[0][mt], ab + 8192 + mt * 1024);
        #pragma unroll
        for (int nt = 0; nt < 8; nt++)
            lds64(bfr[0][nt], bb + 8192 + nt * 512);
        #pragma unroll
        for (int mt = 0; mt < 4; mt++)
            #pragma unroll
            for (int nt = 0; nt < 8; nt++)
                mma_f16(acc[mt][nt], afr[1][mt], bfr[1][nt]);

        // step 3 loads, step-2 MMAs
        #pragma unroll
        for (int mt = 0; mt < 4; mt++)
            lds128(afr[1][mt], ab + 8192 + 512 + mt * 1024);
        #pragma unroll
        for (int nt = 0; nt < 8; nt++)
            lds64(bfr[1][nt], bb + 8192 + 256 + nt * 512);
        #pragma unroll
        for (int mt = 0; mt < 4; mt++)
            #pragma unroll
            for (int nt = 0; nt < 8; nt++)
                mma_f16(acc[mt][nt], afr[0][mt], bfr[0][nt]);

        // step-3 MMAs
        #pragma unroll
        for (int mt = 0; mt < 4; mt++)
            #pragma unroll
            for (int nt = 0; nt < 8; nt++)
                mma_f16(acc[mt][nt], afr[1][mt], bfr[1][nt]);

        // advance incremental state
        st += STG;     if (st     == STAGES * STG) st = 0;
        stFill += STG; if (stFill == STAGES * STG) stFill = 0;
        rA += A_STG;
        rB += B_STG;
    }

    // ---- epilogue ----
    const int fr = lane >> 2;
    const int lrow0 = wm * 64 + fr;
    const int lcol0 = wn * 64 + 2 * (lane & 3);

    if (bid < FULL_TILES) {
        const int orow0 = m128 * 128 + lrow0;
        const int ocol0 = n128 * 128 + lcol0;
        float2 bv[8];
        #pragma unroll
        for (int nt = 0; nt < 8; nt++)
            bv[nt] = *reinterpret_cast<const float2*>(bias + ocol0 + nt * 8);
        #pragma unroll
        for (int mt = 0; mt < 4; mt++) {
            const int r0 = orow0 + mt * 16;
            #pragma unroll
            for (int nt = 0; nt < 8; nt++) {
                const int col = ocol0 + nt * 8;
                float2 v0 = { acc[mt][nt][0] + bv[nt].x, acc[mt][nt][1] + bv[nt].y };
                float2 v1 = { acc[mt][nt][2] + bv[nt].x, acc[mt][nt][3] + bv[nt].y };
                *reinterpret_cast<float2*>(out + (size_t)r0 * KDIM + col) = v0;
                *reinterpret_cast<float2*>(out + (size_t)(r0 + 8) * KDIM + col) = v1;
            }
        }
    } else {
        float* pt = part + (size_t)(bid - FULL_TILES) * (128 * 128);
        #pragma unroll
        for (int mt = 0; mt < 4; mt++) {
            const int r0 = lrow0 + mt * 16;
            #pragma unroll
            for (int nt = 0; nt < 8; nt++) {
                const int col = lcol0 + nt * 8;
                float2 v0 = { acc[mt][nt][0], acc[mt][nt][1] };
                float2 v1 = { acc[mt][nt][2], acc[mt][nt][3] };
                *reinterpret_cast<float2*>(pt + r0 * 128 + col) = v0;
                *reinterpret_cast<float2*>(pt + (r0 + 8) * 128 + col) = v1;
            }
        }
    }
}

// ---------------------------------------------------------------------------
// Reduce: out(tile 888+j) = part[2j] + part[2j+1] + bias.
// ---------------------------------------------------------------------------
__global__ void __launch_bounds__(256) reduce_split(const float* __restrict__ part,
                                                    const float* __restrict__ bias,
                                                    float* __restrict__ out) {
    const int idx = blockIdx.x * 256 + threadIdx.x;
    const int j   = idx >> 12;
    const int e   = idx & 4095;
    const int r   = e >> 5;
    const int c   = (e & 31) * 4;
    const int t   = FULL_TILES + j;
    const int orow = (t & 31) * 128 + r;
    const int ocol = (t >> 5) * 128 + c;

    const float4 p0 = *reinterpret_cast<const float4*>(
        part + ((size_t)(2 * j) * 16384 + r * 128 + c));
    const float4 p1 = *reinterpret_cast<const float4*>(
        part + ((size_t)(2 * j + 1) * 16384 + r * 128 + c));
    const float4 bv = *reinterpret_cast<const float4*>(bias + ocol);
    float4 o;
    o.x = p0.x + p1.x + bv.x;
    o.y = p0.y + p1.y + bv.y;
    o.z = p0.z + p1.z + bv.z;
    o.w = p0.w + p1.w + bv.w;
    *reinterpret_cast<float4*>(out + (size_t)orow * KDIM + ocol) = o;
}

// ---------------------------------------------------------------------------
extern "C" void kernel_launch(void* const* d_in, const int* in_sizes, int n_in,
                              void* d_out, int out_size) {
    const float* x    = (const float*)d_in[0];
    const float* w    = (const float*)d_in[1];
    const float* bias = (const float*)d_in[2];
    float* out        = (float*)d_out;

    void* gx = nullptr;
    void* gw = nullptr;
    void* gp = nullptr;
    cudaGetSymbolAddress(&gx, g_xa);
    cudaGetSymbolAddress(&gw, g_wb);
    cudaGetSymbolAddress(&gp, g_part);

    static bool attr_set = false;  // host-side only
    if (!attr_set) {
        cudaFuncSetAttribute(gemm_f16_mma,
                             cudaFuncAttributeMaxDynamicSharedMemorySize, SMEM_TOTAL);
        attr_set = true;
    }

    prep_ab<<<6144, 256>>>(x, w, (uint4*)gx, (uint2*)gw);

    gemm_f16_mma<<<GRID_GEMM, 128, SMEM_TOTAL>>>(
        (const __half*)gx, (const __half*)gw, bias, out, (float*)gp);

    reduce_split<<<2176, 256>>>((const float*)gp, bias, out);
}